// round 2
// baseline (speedup 1.0000x reference)
#include <cuda_runtime.h>

// linear_sig: depth-3 path signature (B=2048, T=128, C=8) + linear head (584 -> 10)
//
// R2: (a) packed fma.rn.f32x2 throughout the step update (halves fma-pipe instrs),
//     (b) 2 warps per row via Chen's identity: each warp signs half the path,
//         halves merge through shared memory:
//           S1c = S1a + S1b
//           S2c[i,j] = S2a + S2b + S1a[i] S1b[j]
//           S3c[i,j,l] = S3a + S3b + S2a[i,j] S1b[l] + S1a[i] S2b[j,l]
// Lane r owns i = r>>2, j in {2(r&3), 2(r&3)+1}: 2 S2 scalars + 16 S3 values
// (kept as 8 packed f32x2 regs). Second-half warp pads one zero increment so
// both halves run a fixed 64-step loop (exp(0) = identity).

constexpr int TT      = 128;
constexpr int CC      = 8;
constexpr int NOUT    = 10;
constexpr int SIGDIM  = 584;      // 8 + 64 + 512
constexpr int WARPS   = 8;        // 4 row-pairs per block
constexpr int PAIRS   = WARPS / 2;
constexpr int THREADS = WARPS * 32;
constexpr int ROWBUF  = 66;       // 65 rows used, padded

using ull = unsigned long long;

__device__ __forceinline__ ull pk(float lo, float hi) {
    ull r; asm("mov.b64 %0,{%1,%2};" : "=l"(r) : "f"(lo), "f"(hi)); return r;
}
__device__ __forceinline__ float2 upk(ull v) {
    float2 f; asm("mov.b64 {%0,%1},%2;" : "=f"(f.x), "=f"(f.y) : "l"(v)); return f;
}
__device__ __forceinline__ ull f2fma(ull a, ull b, ull c) {
    ull d; asm("fma.rn.f32x2 %0,%1,%2,%3;" : "=l"(d) : "l"(a), "l"(b), "l"(c)); return d;
}

__global__ __launch_bounds__(THREADS, 3)
void sig_linear_kernel(const float* __restrict__ X,
                       const float* __restrict__ W,
                       const float* __restrict__ Bv,
                       float* __restrict__ out, int nB)
{
    __shared__ __align__(16) float sW2[NOUT * 32 * 19];       // reordered W, stride 19
    __shared__ float sb[NOUT];
    __shared__ __align__(16) float sx[PAIRS][2][ROWBUF * CC]; // X staging; aliased as combine buf

    // Reordered W: sW2[n][lane][k]
    //   k=0,1   -> W[n, 8 + 2*lane + k]           (S2 pair)
    //   k=2..17 -> W[n, 72 + 16*lane + (k-2)]     (S3 block)
    //   k=18    -> (lane%4==0) ? W[n, lane/4] : 0 (S1, dedup across replicas)
    for (int idx = threadIdx.x; idx < NOUT * 32 * 19; idx += THREADS) {
        int n   = idx / (32 * 19);
        int rem = idx - n * (32 * 19);
        int r   = rem / 19;
        int k   = rem - r * 19;
        const float* Wn = W + n * SIGDIM;
        float v;
        if (k < 2)       v = Wn[8 + 2 * r + k];
        else if (k < 18) v = Wn[72 + 16 * r + (k - 2)];
        else             v = ((r & 3) == 0) ? Wn[r >> 2] : 0.0f;
        sW2[idx] = v;
    }
    if (threadIdx.x < NOUT) sb[threadIdx.x] = Bv[threadIdx.x];
    __syncthreads();

    const int wib  = threadIdx.x >> 5;
    const int lane = threadIdx.x & 31;
    const int pair = wib >> 1;
    const int half = wib & 1;                  // 0 = first half (also combiner)
    const int row  = blockIdx.x * PAIRS + pair;
    const bool active = row < nB;

    const int i0 = lane >> 2;
    const int j0 = (lane & 3) << 1;
    const int t0 = half ? 64 : 0;

    float* sxw = &sx[pair][half][0];

    // Stage 65 rows (second half duplicates row 127 -> one zero increment)
    if (active) {
        const float* xb = X + (size_t)row * (TT * CC);
        for (int r = lane; r < 65; r += 32) {
            int gr = t0 + r; if (gr > TT - 1) gr = TT - 1;
            float4 a = *(const float4*)(xb + gr * 8);
            float4 c = *(const float4*)(xb + gr * 8 + 4);
            *(float4*)(sxw + r * 8)     = a;
            *(float4*)(sxw + r * 8 + 4) = c;
        }
    }
    __syncwarp();

    const ull NEG1 = pk(-1.0f, -1.0f);
    const ull CA   = pk(1.0f / 6.0f, 0.5f);    // (u,v) coeffs on dxi
    const ull CB   = pk(0.5f, 1.0f);           // (S1/2, S1) update coeffs

    ull S1p = pk(0.f, 0.f);                    // (S1i/2, S1i)
    ull S2p = pk(0.f, 0.f);                    // (S2[i,j0], S2[i,j0+1])
    ull S3p[8];                                // m<4: (S3[i,j0,2m],S3[i,j0,2m+1]); m>=4: j0+1
    #pragma unroll
    for (int m = 0; m < 8; m++) S3p[m] = pk(0.f, 0.f);

    if (active) {
        const ull* r0 = (const ull*)sxw;
        ull xp0 = r0[0], xp1 = r0[1], xp2 = r0[2], xp3 = r0[3];
        ull xpj = *(const ull*)(sxw + j0);
        float xpi = sxw[i0];

        #pragma unroll 8
        for (int s = 1; s <= 64; s++) {
            const float* rw = sxw + s * 8;
            const ull* rp = (const ull*)rw;
            ull xn0 = rp[0], xn1 = rp[1], xn2 = rp[2], xn3 = rp[3];
            ull xnj = *(const ull*)(rw + j0);
            float xni = rw[i0];

            ull d0 = f2fma(xp0, NEG1, xn0);
            ull d1 = f2fma(xp1, NEG1, xn1);
            ull d2 = f2fma(xp2, NEG1, xn2);
            ull d3 = f2fma(xp3, NEG1, xn3);
            ull dj = f2fma(xpj, NEG1, xnj);
            float dxi = xni - xpi;
            xp0 = xn0; xp1 = xn1; xp2 = xn2; xp3 = xn3; xpj = xnj; xpi = xni;

            ull dd = pk(dxi, dxi);
            ull uv = f2fma(dd, CA, S1p);       // (u, v) from OLD S1
            S1p    = f2fma(dd, CB, S1p);
            float2 uvf = upk(uv);
            ull t3 = f2fma(dj, pk(uvf.x, uvf.x), S2p);   // OLD S2
            S2p    = f2fma(dj, pk(uvf.y, uvf.y), S2p);
            float2 t3f = upk(t3);
            ull T0 = pk(t3f.x, t3f.x);
            ull T1 = pk(t3f.y, t3f.y);

            S3p[0] = f2fma(d0, T0, S3p[0]);
            S3p[1] = f2fma(d1, T0, S3p[1]);
            S3p[2] = f2fma(d2, T0, S3p[2]);
            S3p[3] = f2fma(d3, T0, S3p[3]);
            S3p[4] = f2fma(d0, T1, S3p[4]);
            S3p[5] = f2fma(d1, T1, S3p[5]);
            S3p[6] = f2fma(d2, T1, S3p[6]);
            S3p[7] = f2fma(d3, T1, S3p[7]);
        }
    }
    __syncthreads();   // everyone done reading sx -> safe to alias

    // Combine buffer overlays the pair's staging area:
    //   cb[0..7]  = S1b, cb[8..71] = S2b, cb[72 + lane*17 + k] = S3b[lane][k]
    float* cb = &sx[pair][0][0];
    if (active && half == 1) {
        float2 s2f = upk(S2p);
        float2 s1f = upk(S1p);
        if ((lane & 3) == 0) cb[i0] = s1f.y;
        cb[8 + i0 * 8 + j0]     = s2f.x;
        cb[8 + i0 * 8 + j0 + 1] = s2f.y;
        float* c3 = cb + 72 + lane * 17;
        #pragma unroll
        for (int m = 0; m < 8; m++) {
            float2 v = upk(S3p[m]);
            c3[2 * m]     = v.x;
            c3[2 * m + 1] = v.y;
        }
    }
    __syncthreads();

    if (active && half == 0) {
        float2 s2a = upk(S2p);
        float  s1a = upk(S1p).y;

        float S3a[16];
        #pragma unroll
        for (int m = 0; m < 8; m++) {
            float2 v = upk(S3p[m]);
            S3a[2 * m] = v.x; S3a[2 * m + 1] = v.y;
        }

        const float* c3 = cb + 72 + lane * 17;
        float S1c  = s1a + cb[i0];
        float S2c0 = s2a.x + cb[8 + i0 * 8 + j0]     + s1a * cb[j0];
        float S2c1 = s2a.y + cb[8 + i0 * 8 + j0 + 1] + s1a * cb[j0 + 1];

        float S3c[16];
        #pragma unroll
        for (int l = 0; l < 8; l++) {
            float s1bl = cb[l];
            S3c[l]     = S3a[l]     + c3[l]     + s2a.x * s1bl + s1a * cb[8 + j0 * 8 + l];
            S3c[8 + l] = S3a[8 + l] + c3[8 + l] + s2a.y * s1bl + s1a * cb[8 + (j0 + 1) * 8 + l];
        }

        // Epilogue: out[row, n] = b[n] + <sig, W[n]>
        float* orow = out + (size_t)row * NOUT;
        #pragma unroll
        for (int n = 0; n < NOUT; n++) {
            const float* wn = sW2 + n * (32 * 19) + lane * 19;  // stride 19: conflict-free
            float p = S2c0 * wn[0] + S2c1 * wn[1] + S1c * wn[18];
            #pragma unroll
            for (int k = 0; k < 16; k++) p += S3c[k] * wn[2 + k];
            #pragma unroll
            for (int off = 16; off; off >>= 1)
                p += __shfl_xor_sync(0xffffffffu, p, off);
            if (lane == 0) orow[n] = p + sb[n];
        }
    }
}

extern "C" void kernel_launch(void* const* d_in, const int* in_sizes, int n_in,
                              void* d_out, int out_size) {
    const float* X  = (const float*)d_in[0];
    const float* W  = (const float*)d_in[1];
    const float* b  = (const float*)d_in[2];
    float* out      = (float*)d_out;
    int nB = in_sizes[0] / (TT * CC);                 // 2048
    int grid = (nB + PAIRS - 1) / PAIRS;              // 512 blocks
    sig_linear_kernel<<<grid, THREADS>>>(X, W, b, out, nB);
}

// round 3
// speedup vs baseline: 1.0813x; 1.0813x over previous
#include <cuda_runtime.h>

// linear_sig: depth-3 path signature (B=2048, T=128, C=8) + linear head (584 -> 10)
//
// R3: scalar FFMA body (f32x2 regression reverted), dx precomputed into shared
// during staging (inner loop has zero subtractions and no x carry state),
// split-2 across T via Chen's identity:
//   S1c = S1a + S1b
//   S2c[i,j]   = S2a + S2b + S1a[i] S1b[j]
//   S3c[i,j,l] = S3a + S3b + S2a[i,j] S1b[l] + S1a[i] S2b[j,l]
// Lane r owns i = r>>2, j in {2(r&3), 2(r&3)+1}: 2 S2 scalars + 16 S3 regs.

constexpr int TT      = 128;
constexpr int CC      = 8;
constexpr int NOUT    = 10;
constexpr int SIGDIM  = 584;      // 8 + 64 + 512
constexpr int WARPS   = 8;        // 4 row-pairs per block
constexpr int PAIRS   = WARPS / 2;
constexpr int THREADS = WARPS * 32;
constexpr int STEPS   = 64;       // increments per half-warp

__global__ __launch_bounds__(THREADS, 4)
void sig_linear_kernel(const float* __restrict__ X,
                       const float* __restrict__ W,
                       const float* __restrict__ Bv,
                       float* __restrict__ out, int nB)
{
    __shared__ __align__(16) float sW2[NOUT * 32 * 19];        // reordered W, stride 19
    __shared__ float sb[NOUT];
    __shared__ __align__(16) float sx[PAIRS][2][STEPS * CC];   // dx staging; aliased as combine buf

    // Reordered W: sW2[n][lane][k]
    //   k=0,1   -> W[n, 8 + 2*lane + k]           (S2 pair)
    //   k=2..17 -> W[n, 72 + 16*lane + (k-2)]     (S3 block)
    //   k=18    -> (lane%4==0) ? W[n, lane/4] : 0 (S1, dedup across replicas)
    for (int idx = threadIdx.x; idx < NOUT * 32 * 19; idx += THREADS) {
        int n   = idx / (32 * 19);
        int rem = idx - n * (32 * 19);
        int r   = rem / 19;
        int k   = rem - r * 19;
        const float* Wn = W + n * SIGDIM;
        float v;
        if (k < 2)       v = Wn[8 + 2 * r + k];
        else if (k < 18) v = Wn[72 + 16 * r + (k - 2)];
        else             v = ((r & 3) == 0) ? Wn[r >> 2] : 0.0f;
        sW2[idx] = v;
    }
    if (threadIdx.x < NOUT) sb[threadIdx.x] = Bv[threadIdx.x];
    __syncthreads();

    const int wib  = threadIdx.x >> 5;
    const int lane = threadIdx.x & 31;
    const int pair = wib >> 1;
    const int half = wib & 1;                  // 0 = first half (also combiner)
    const int row  = blockIdx.x * PAIRS + pair;
    const bool active = row < nB;

    const int i0 = lane >> 2;
    const int j0 = (lane & 3) << 1;
    const int t0 = half ? STEPS : 0;

    float* sxw = &sx[pair][half][0];

    // Stage dx: increment s covers x[t0+s+1]-x[t0+s]; global index 127 pads to 0.
    if (active) {
        const float* xb = X + (size_t)row * (TT * CC);
        #pragma unroll
        for (int s = lane; s < STEPS; s += 32) {
            int g = t0 + s;
            float4 da, db;
            if (g < TT - 1) {
                float4 a0 = *(const float4*)(xb + g * 8);
                float4 a1 = *(const float4*)(xb + g * 8 + 4);
                float4 b0 = *(const float4*)(xb + (g + 1) * 8);
                float4 b1 = *(const float4*)(xb + (g + 1) * 8 + 4);
                da = make_float4(b0.x - a0.x, b0.y - a0.y, b0.z - a0.z, b0.w - a0.w);
                db = make_float4(b1.x - a1.x, b1.y - a1.y, b1.z - a1.z, b1.w - a1.w);
            } else {
                da = make_float4(0.f, 0.f, 0.f, 0.f);
                db = da;
            }
            *(float4*)(sxw + s * 8)     = da;
            *(float4*)(sxw + s * 8 + 4) = db;
        }
    }
    __syncwarp();

    float S1  = 0.f;   // S1[i]
    float S1h = 0.f;   // S1[i] / 2
    float S20 = 0.f, S21 = 0.f;
    float S3[16];
    #pragma unroll
    for (int k = 0; k < 16; k++) S3[k] = 0.f;

    if (active) {
        #pragma unroll 8
        for (int s = 0; s < STEPS; s++) {
            const float* rw = sxw + s * 8;
            float4 dA = *(const float4*)(rw);      // broadcast LDS.128
            float4 dB = *(const float4*)(rw + 4);
            float  dxi = rw[i0];                   // lane-selected channel
            float2 dxj = *(const float2*)(rw + j0);

            float u   = dxi * (1.f / 6.f) + S1h;   // old S1/2 baked in
            float v   = dxi * 0.5f + S1;
            float t30 = dxj.x * u + S20;           // old S2
            float t31 = dxj.y * u + S21;

            S3[0]  += t30 * dA.x;  S3[1]  += t30 * dA.y;
            S3[2]  += t30 * dA.z;  S3[3]  += t30 * dA.w;
            S3[4]  += t30 * dB.x;  S3[5]  += t30 * dB.y;
            S3[6]  += t30 * dB.z;  S3[7]  += t30 * dB.w;
            S3[8]  += t31 * dA.x;  S3[9]  += t31 * dA.y;
            S3[10] += t31 * dA.z;  S3[11] += t31 * dA.w;
            S3[12] += t31 * dB.x;  S3[13] += t31 * dB.y;
            S3[14] += t31 * dB.z;  S3[15] += t31 * dB.w;

            S20 += dxj.x * v;
            S21 += dxj.y * v;
            S1  += dxi;
            S1h += dxi * 0.5f;
        }
    }
    __syncthreads();   // all reads of sx done -> safe to alias

    // Combine buffer overlays the pair's staging area (1024 floats available):
    //   cb[0..7] = S1b, cb[8..71] = S2b, cb[72 + lane*17 + k] = S3b[lane][k]
    float* cb = &sx[pair][0][0];
    if (active && half == 1) {
        if ((lane & 3) == 0) cb[i0] = S1;
        cb[8 + i0 * 8 + j0]     = S20;
        cb[8 + i0 * 8 + j0 + 1] = S21;
        float* c3 = cb + 72 + lane * 17;
        #pragma unroll
        for (int k = 0; k < 16; k++) c3[k] = S3[k];
    }
    __syncthreads();

    if (active && half == 0) {
        const float* c3 = cb + 72 + lane * 17;
        float S1c  = S1 + cb[i0];
        float S2c0 = S20 + cb[8 + i0 * 8 + j0]     + S1 * cb[j0];
        float S2c1 = S21 + cb[8 + i0 * 8 + j0 + 1] + S1 * cb[j0 + 1];

        float S3c[16];
        #pragma unroll
        for (int l = 0; l < 8; l++) {
            float s1bl = cb[l];
            S3c[l]     = S3[l]     + c3[l]     + S20 * s1bl + S1 * cb[8 + j0 * 8 + l];
            S3c[8 + l] = S3[8 + l] + c3[8 + l] + S21 * s1bl + S1 * cb[8 + (j0 + 1) * 8 + l];
        }

        // Epilogue: out[row, n] = b[n] + <sig, W[n]>
        float* orow = out + (size_t)row * NOUT;
        #pragma unroll
        for (int n = 0; n < NOUT; n++) {
            const float* wn = sW2 + n * (32 * 19) + lane * 19;  // stride 19: conflict-free
            float p = S2c0 * wn[0] + S2c1 * wn[1] + S1c * wn[18];
            #pragma unroll
            for (int k = 0; k < 16; k++) p += S3c[k] * wn[2 + k];
            #pragma unroll
            for (int off = 16; off; off >>= 1)
                p += __shfl_xor_sync(0xffffffffu, p, off);
            if (lane == 0) orow[n] = p + sb[n];
        }
    }
}

extern "C" void kernel_launch(void* const* d_in, const int* in_sizes, int n_in,
                              void* d_out, int out_size) {
    const float* X  = (const float*)d_in[0];
    const float* W  = (const float*)d_in[1];
    const float* b  = (const float*)d_in[2];
    float* out      = (float*)d_out;
    int nB = in_sizes[0] / (TT * CC);                 // 2048
    int grid = (nB + PAIRS - 1) / PAIRS;              // 512 blocks
    sig_linear_kernel<<<grid, THREADS>>>(X, W, b, out, nB);
}

// round 5
// speedup vs baseline: 1.2594x; 1.1647x over previous
#include <cuda_runtime.h>

// linear_sig: depth-3 path signature (B=2048, T=128, C=8) + linear head (584 -> 10)
//
// R5 = R4 resubmit (R4 bench failed on infra, theory untested).
// fma-pipe is the binding resource (FFMA rt_SMSP=2 => FFMA-heavy code caps
// issue at ~50-58%). The 16 essential S3 FMAs/step are packed into 8
// fma.rn.f32x2 (dx pairs come free from LDS.128 register adjacency; only 2
// MOVs/step for the t30/t31 pair-broadcasts). Aux math stays scalar with
// FFMA-imm (rt=1) where possible. W reorder done by a one-shot prep kernel;
// epilogue reads reordered W from L2. Keeps R3's dx staging + split-2 Chen
// combine:
//   S1c = S1a + S1b
//   S2c[i,j]   = S2a + S2b + S1a[i] S1b[j]
//   S3c[i,j,l] = S3a + S3b + S2a[i,j] S1b[l] + S1a[i] S2b[j,l]

constexpr int TT      = 128;
constexpr int CC      = 8;
constexpr int NOUT    = 10;
constexpr int SIGDIM  = 584;      // 8 + 64 + 512
constexpr int WARPS   = 8;        // 4 row-pairs per block
constexpr int PAIRS   = WARPS / 2;
constexpr int THREADS = WARPS * 32;
constexpr int STEPS   = 64;       // increments per half-warp
constexpr int W2SZ    = NOUT * 32 * 19;   // 6080

__device__ float g_W2[W2SZ];      // reordered W, written by prep kernel

using ull = unsigned long long;

__device__ __forceinline__ ull dup2(float x) {
    ull r; asm("mov.b64 %0,{%1,%1};" : "=l"(r) : "f"(x)); return r;
}
__device__ __forceinline__ float2 upk(ull v) {
    float2 f; asm("mov.b64 {%0,%1},%2;" : "=f"(f.x), "=f"(f.y) : "l"(v)); return f;
}
__device__ __forceinline__ void f2fma(ull& acc, ull a, ull b) {
    asm("fma.rn.f32x2 %0,%1,%2,%0;" : "+l"(acc) : "l"(a), "l"(b));
}

// Reorder W once: g_W2[n*608 + r*19 + k]
//   k=0,1   -> W[n, 8 + 2r + k]            (S2 pair)
//   k=2..17 -> W[n, 72 + 16r + (k-2)]      (S3 block)
//   k=18    -> (r%4==0) ? W[n, r/4] : 0    (S1, dedup across replicas)
__global__ __launch_bounds__(256) void prep_w_kernel(const float* __restrict__ W) {
    int idx = blockIdx.x * blockDim.x + threadIdx.x;
    if (idx >= W2SZ) return;
    int n   = idx / (32 * 19);
    int rem = idx - n * (32 * 19);
    int r   = rem / 19;
    int k   = rem - r * 19;
    const float* Wn = W + n * SIGDIM;
    float v;
    if (k < 2)       v = Wn[8 + 2 * r + k];
    else if (k < 18) v = Wn[72 + 16 * r + (k - 2)];
    else             v = ((r & 3) == 0) ? Wn[r >> 2] : 0.0f;
    g_W2[idx] = v;
}

__global__ __launch_bounds__(THREADS, 3)
void sig_linear_kernel(const float* __restrict__ X,
                       const float* __restrict__ Bv,
                       float* __restrict__ out, int nB)
{
    __shared__ __align__(16) float sx[PAIRS][2][STEPS * CC];  // dx staging / combine buf

    const int wib  = threadIdx.x >> 5;
    const int lane = threadIdx.x & 31;
    const int pair = wib >> 1;
    const int half = wib & 1;                  // 0 = first half (also combiner)
    const int row  = blockIdx.x * PAIRS + pair;
    const bool active = row < nB;

    const int i0 = lane >> 2;
    const int j0 = (lane & 3) << 1;
    const int t0 = half ? STEPS : 0;

    float* sxw = &sx[pair][half][0];

    // Stage dx: slot s holds x[t0+s+1]-x[t0+s]; global index 127 pads to 0.
    if (active) {
        const float* xb = X + (size_t)row * (TT * CC);
        #pragma unroll
        for (int s = lane; s < STEPS; s += 32) {
            int g = t0 + s;
            float4 da, db;
            if (g < TT - 1) {
                float4 a0 = *(const float4*)(xb + g * 8);
                float4 a1 = *(const float4*)(xb + g * 8 + 4);
                float4 b0 = *(const float4*)(xb + (g + 1) * 8);
                float4 b1 = *(const float4*)(xb + (g + 1) * 8 + 4);
                da = make_float4(b0.x - a0.x, b0.y - a0.y, b0.z - a0.z, b0.w - a0.w);
                db = make_float4(b1.x - a1.x, b1.y - a1.y, b1.z - a1.z, b1.w - a1.w);
            } else {
                da = make_float4(0.f, 0.f, 0.f, 0.f);
                db = da;
            }
            *(float4*)(sxw + s * 8)     = da;
            *(float4*)(sxw + s * 8 + 4) = db;
        }
    }
    __syncwarp();

    float S1 = 0.f, S1h = 0.f;            // S1[i], S1[i]/2
    float S20 = 0.f, S21 = 0.f;
    ull S3p[8];                            // m<4: (S3[i,j0,2m], S3[i,j0,2m+1]); m>=4: j0+1
    #pragma unroll
    for (int m = 0; m < 8; m++) S3p[m] = 0ull;

    if (active) {
        #pragma unroll 8
        for (int s = 0; s < STEPS; s++) {
            const float* rw = sxw + s * 8;
            ulonglong2 qa = *(const ulonglong2*)(rw);      // (dx0,dx1),(dx2,dx3)
            ulonglong2 qb = *(const ulonglong2*)(rw + 4);  // (dx4,dx5),(dx6,dx7)
            float2 dxj = *(const float2*)(rw + j0);
            float  dxi = rw[i0];

            float u   = fmaf(dxi, 1.f / 6.f, S1h);         // OLD S1 baked in
            float v   = fmaf(dxi, 0.5f, S1);
            float t30 = fmaf(dxj.x, u, S20);               // OLD S2
            float t31 = fmaf(dxj.y, u, S21);
            ull T0 = dup2(t30);
            ull T1 = dup2(t31);

            f2fma(S3p[0], qa.x, T0);
            f2fma(S3p[1], qa.y, T0);
            f2fma(S3p[2], qb.x, T0);
            f2fma(S3p[3], qb.y, T0);
            f2fma(S3p[4], qa.x, T1);
            f2fma(S3p[5], qa.y, T1);
            f2fma(S3p[6], qb.x, T1);
            f2fma(S3p[7], qb.y, T1);

            S20 = fmaf(dxj.x, v, S20);
            S21 = fmaf(dxj.y, v, S21);
            S1 += dxi;
            S1h = fmaf(dxi, 0.5f, S1h);
        }
    }
    __syncthreads();   // all reads of sx done -> safe to alias

    // Combine buffer overlays the pair's staging area:
    //   cb[0..7] = S1b, cb[8..71] = S2b, cb[72 + lane*17 + k] = S3b[lane][k]
    float* cb = &sx[pair][0][0];
    if (active && half == 1) {
        if ((lane & 3) == 0) cb[i0] = S1;
        cb[8 + i0 * 8 + j0]     = S20;
        cb[8 + i0 * 8 + j0 + 1] = S21;
        float* c3 = cb + 72 + lane * 17;
        #pragma unroll
        for (int m = 0; m < 8; m++) {
            float2 f = upk(S3p[m]);
            c3[2 * m]     = f.x;
            c3[2 * m + 1] = f.y;
        }
    }
    __syncthreads();

    if (active && half == 0) {
        float S3a[16];
        #pragma unroll
        for (int m = 0; m < 8; m++) {
            float2 f = upk(S3p[m]);
            S3a[2 * m] = f.x; S3a[2 * m + 1] = f.y;
        }

        const float* c3 = cb + 72 + lane * 17;
        float S1c  = S1 + cb[i0];
        float S2c0 = S20 + cb[8 + i0 * 8 + j0]     + S1 * cb[j0];
        float S2c1 = S21 + cb[8 + i0 * 8 + j0 + 1] + S1 * cb[j0 + 1];

        float S3c[16];
        #pragma unroll
        for (int l = 0; l < 8; l++) {
            float s1bl = cb[l];
            S3c[l]     = S3a[l]     + c3[l]     + S20 * s1bl + S1 * cb[8 + j0 * 8 + l];
            S3c[8 + l] = S3a[8 + l] + c3[8 + l] + S21 * s1bl + S1 * cb[8 + (j0 + 1) * 8 + l];
        }

        // Epilogue: out[row, n] = b[n] + <sig, W[n]>  (reordered W from L2)
        float* orow = out + (size_t)row * NOUT;
        #pragma unroll
        for (int n = 0; n < NOUT; n++) {
            const float* wn = g_W2 + n * (32 * 19) + lane * 19;
            float p = S2c0 * __ldg(wn) + S2c1 * __ldg(wn + 1) + S1c * __ldg(wn + 18);
            #pragma unroll
            for (int k = 0; k < 16; k++) p += S3c[k] * __ldg(wn + 2 + k);
            #pragma unroll
            for (int off = 16; off; off >>= 1)
                p += __shfl_xor_sync(0xffffffffu, p, off);
            if (lane == 0) orow[n] = p + __ldg(Bv + n);
        }
    }
}

extern "C" void kernel_launch(void* const* d_in, const int* in_sizes, int n_in,
                              void* d_out, int out_size) {
    const float* X  = (const float*)d_in[0];
    const float* W  = (const float*)d_in[1];
    const float* b  = (const float*)d_in[2];
    float* out      = (float*)d_out;
    int nB = in_sizes[0] / (TT * CC);                 // 2048
    prep_w_kernel<<<(W2SZ + 255) / 256, 256>>>(W);
    int grid = (nB + PAIRS - 1) / PAIRS;              // 512 blocks
    sig_linear_kernel<<<grid, THREADS>>>(X, b, out, nB);
}

// round 7
// speedup vs baseline: 1.4514x; 1.1525x over previous
#include <cuda_runtime.h>

// linear_sig: depth-3 path signature (B=2048, T=128, C=8) + linear head (584 -> 10)
//
// R7 = R6 resubmit (R6 bench failed on infra, theory untested).
// R5 step body (8x fma.rn.f32x2 S3 update, 2 pack-MOVs, scalar aux) kept;
// occupancy bought back: unroll 8->4 (halves hoisted-load regs), 128-thread
// blocks with __launch_bounds__(128,8) (<=64 regs, 32 warps/SM ceiling, finer
// block balance: 1024 blocks over 148 SMs). Split-2 over T via Chen:
//   S1c = S1a + S1b
//   S2c[i,j]   = S2a + S2b + S1a[i] S1b[j]
//   S3c[i,j,l] = S3a + S3b + S2a[i,j] S1b[l] + S1a[i] S2b[j,l]
// Lane r owns i = r>>2, j in {2(r&3), 2(r&3)+1}: 2 S2 scalars + 8 packed S3.

constexpr int TT      = 128;
constexpr int CC      = 8;
constexpr int NOUT    = 10;
constexpr int SIGDIM  = 584;      // 8 + 64 + 512
constexpr int WARPS   = 4;        // 2 row-pairs per block
constexpr int PAIRS   = WARPS / 2;
constexpr int THREADS = WARPS * 32;   // 128
constexpr int STEPS   = 64;       // increments per half-warp
constexpr int W2SZ    = NOUT * 32 * 19;   // 6080

__device__ float g_W2[W2SZ];      // reordered W, written by prep kernel

using ull = unsigned long long;

__device__ __forceinline__ ull dup2(float x) {
    ull r; asm("mov.b64 %0,{%1,%1};" : "=l"(r) : "f"(x)); return r;
}
__device__ __forceinline__ float2 upk(ull v) {
    float2 f; asm("mov.b64 {%0,%1},%2;" : "=f"(f.x), "=f"(f.y) : "l"(v)); return f;
}
__device__ __forceinline__ void f2fma(ull& acc, ull a, ull b) {
    asm("fma.rn.f32x2 %0,%1,%2,%0;" : "+l"(acc) : "l"(a), "l"(b));
}

// Reorder W once: g_W2[n*608 + r*19 + k]
//   k=0,1   -> W[n, 8 + 2r + k]            (S2 pair)
//   k=2..17 -> W[n, 72 + 16r + (k-2)]      (S3 block)
//   k=18    -> (r%4==0) ? W[n, r/4] : 0    (S1, dedup across replicas)
__global__ __launch_bounds__(256) void prep_w_kernel(const float* __restrict__ W) {
    int idx = blockIdx.x * blockDim.x + threadIdx.x;
    if (idx >= W2SZ) return;
    int n   = idx / (32 * 19);
    int rem = idx - n * (32 * 19);
    int r   = rem / 19;
    int k   = rem - r * 19;
    const float* Wn = W + n * SIGDIM;
    float v;
    if (k < 2)       v = Wn[8 + 2 * r + k];
    else if (k < 18) v = Wn[72 + 16 * r + (k - 2)];
    else             v = ((r & 3) == 0) ? Wn[r >> 2] : 0.0f;
    g_W2[idx] = v;
}

__global__ __launch_bounds__(THREADS, 8)
void sig_linear_kernel(const float* __restrict__ X,
                       const float* __restrict__ Bv,
                       float* __restrict__ out, int nB)
{
    __shared__ __align__(16) float sx[PAIRS][2][STEPS * CC];  // dx staging / combine buf

    const int wib  = threadIdx.x >> 5;
    const int lane = threadIdx.x & 31;
    const int pair = wib >> 1;
    const int half = wib & 1;                  // 0 = first half (also combiner)
    const int row  = blockIdx.x * PAIRS + pair;
    const bool active = row < nB;

    const int i0 = lane >> 2;
    const int j0 = (lane & 3) << 1;
    const int t0 = half ? STEPS : 0;

    float* sxw = &sx[pair][half][0];

    // Stage dx: slot s holds x[t0+s+1]-x[t0+s]; global index 127 pads to 0.
    if (active) {
        const float* xb = X + (size_t)row * (TT * CC);
        #pragma unroll
        for (int s = lane; s < STEPS; s += 32) {
            int g = t0 + s;
            float4 da, db;
            if (g < TT - 1) {
                float4 a0 = *(const float4*)(xb + g * 8);
                float4 a1 = *(const float4*)(xb + g * 8 + 4);
                float4 b0 = *(const float4*)(xb + (g + 1) * 8);
                float4 b1 = *(const float4*)(xb + (g + 1) * 8 + 4);
                da = make_float4(b0.x - a0.x, b0.y - a0.y, b0.z - a0.z, b0.w - a0.w);
                db = make_float4(b1.x - a1.x, b1.y - a1.y, b1.z - a1.z, b1.w - a1.w);
            } else {
                da = make_float4(0.f, 0.f, 0.f, 0.f);
                db = da;
            }
            *(float4*)(sxw + s * 8)     = da;
            *(float4*)(sxw + s * 8 + 4) = db;
        }
    }
    __syncwarp();

    float S1 = 0.f, S1h = 0.f;            // S1[i], S1[i]/2
    float S20 = 0.f, S21 = 0.f;
    ull S3p[8];                            // m<4: (S3[i,j0,2m], S3[i,j0,2m+1]); m>=4: j0+1
    #pragma unroll
    for (int m = 0; m < 8; m++) S3p[m] = 0ull;

    if (active) {
        #pragma unroll 4
        for (int s = 0; s < STEPS; s++) {
            const float* rw = sxw + s * 8;
            ulonglong2 qa = *(const ulonglong2*)(rw);      // (dx0,dx1),(dx2,dx3)
            ulonglong2 qb = *(const ulonglong2*)(rw + 4);  // (dx4,dx5),(dx6,dx7)
            float2 dxj = *(const float2*)(rw + j0);
            float  dxi = rw[i0];

            float u   = fmaf(dxi, 1.f / 6.f, S1h);         // OLD S1 baked in
            float v   = fmaf(dxi, 0.5f, S1);
            float t30 = fmaf(dxj.x, u, S20);               // OLD S2
            float t31 = fmaf(dxj.y, u, S21);
            ull T0 = dup2(t30);
            ull T1 = dup2(t31);

            f2fma(S3p[0], qa.x, T0);
            f2fma(S3p[1], qa.y, T0);
            f2fma(S3p[2], qb.x, T0);
            f2fma(S3p[3], qb.y, T0);
            f2fma(S3p[4], qa.x, T1);
            f2fma(S3p[5], qa.y, T1);
            f2fma(S3p[6], qb.x, T1);
            f2fma(S3p[7], qb.y, T1);

            S20 = fmaf(dxj.x, v, S20);
            S21 = fmaf(dxj.y, v, S21);
            S1 += dxi;
            S1h = fmaf(dxi, 0.5f, S1h);
        }
    }
    __syncthreads();   // all reads of sx done -> safe to alias

    // Combine buffer overlays the pair's staging area:
    //   cb[0..7] = S1b, cb[8..71] = S2b, cb[72 + lane*17 + k] = S3b[lane][k]
    float* cb = &sx[pair][0][0];
    if (active && half == 1) {
        if ((lane & 3) == 0) cb[i0] = S1;
        cb[8 + i0 * 8 + j0]     = S20;
        cb[8 + i0 * 8 + j0 + 1] = S21;
        float* c3 = cb + 72 + lane * 17;
        #pragma unroll
        for (int m = 0; m < 8; m++) {
            float2 f = upk(S3p[m]);
            c3[2 * m]     = f.x;
            c3[2 * m + 1] = f.y;
        }
    }
    __syncthreads();

    if (active && half == 0) {
        float S3a[16];
        #pragma unroll
        for (int m = 0; m < 8; m++) {
            float2 f = upk(S3p[m]);
            S3a[2 * m] = f.x; S3a[2 * m + 1] = f.y;
        }

        const float* c3 = cb + 72 + lane * 17;
        float S1c  = S1 + cb[i0];
        float S2c0 = S20 + cb[8 + i0 * 8 + j0]     + S1 * cb[j0];
        float S2c1 = S21 + cb[8 + i0 * 8 + j0 + 1] + S1 * cb[j0 + 1];

        float S3c[16];
        #pragma unroll
        for (int l = 0; l < 8; l++) {
            float s1bl = cb[l];
            S3c[l]     = S3a[l]     + c3[l]     + S20 * s1bl + S1 * cb[8 + j0 * 8 + l];
            S3c[8 + l] = S3a[8 + l] + c3[8 + l] + S21 * s1bl + S1 * cb[8 + (j0 + 1) * 8 + l];
        }

        // Epilogue: out[row, n] = b[n] + <sig, W[n]>  (reordered W from L2)
        float* orow = out + (size_t)row * NOUT;
        #pragma unroll
        for (int n = 0; n < NOUT; n++) {
            const float* wn = g_W2 + n * (32 * 19) + lane * 19;
            float p = S2c0 * __ldg(wn) + S2c1 * __ldg(wn + 1) + S1c * __ldg(wn + 18);
            #pragma unroll
            for (int k = 0; k < 16; k++) p += S3c[k] * __ldg(wn + 2 + k);
            #pragma unroll
            for (int off = 16; off; off >>= 1)
                p += __shfl_xor_sync(0xffffffffu, p, off);
            if (lane == 0) orow[n] = p + __ldg(Bv + n);
        }
    }
}

extern "C" void kernel_launch(void* const* d_in, const int* in_sizes, int n_in,
                              void* d_out, int out_size) {
    const float* X  = (const float*)d_in[0];
    const float* W  = (const float*)d_in[1];
    const float* b  = (const float*)d_in[2];
    float* out      = (float*)d_out;
    int nB = in_sizes[0] / (TT * CC);                 // 2048
    prep_w_kernel<<<(W2SZ + 255) / 256, 256>>>(W);
    int grid = (nB + PAIRS - 1) / PAIRS;              // 1024 blocks
    sig_linear_kernel<<<grid, THREADS>>>(X, b, out, nB);
}